// round 1
// baseline (speedup 1.0000x reference)
#include <cuda_runtime.h>
#include <math.h>

// Problem constants
#define BB 4
#define HH 16
#define NN 4096
#define DD 64
#define MM 256
#define BH 64            // B*H
#define NSPLIT 8
#define NCHUNK 512       // NN / NSPLIT
#define TN 32            // n-tile inside kernel1
#define TNQ 128          // q rows per block in kernel2
#define EPSF 1e-6f

typedef unsigned long long ull;

// ---------------- scratch (no allocations allowed) ----------------
__device__ float g_ctxp[(size_t)BH * NSPLIT * MM * DD];   // partial contexts, 32 MB
__device__ float g_ksump[(size_t)BH * NSPLIT * MM];       // partial k-sums
__device__ float g_ctx[(size_t)BH * MM * DD];             // reduced contexts, 4 MB
__device__ float g_ksum[(size_t)BH * MM];                 // reduced k-sums

// ---------------- f32x2 helpers (2x fp32 FMA throughput on sm_103a) ----------------
__device__ __forceinline__ ull pack2(float x, float y) {
    ull r; asm("mov.b64 %0, {%1, %2};" : "=l"(r) : "f"(x), "f"(y)); return r;
}
__device__ __forceinline__ void unpack2(ull u, float& x, float& y) {
    asm("mov.b64 {%0, %1}, %2;" : "=f"(x), "=f"(y) : "l"(u));
}
__device__ __forceinline__ ull fma2(ull a, ull b, ull c) {
    ull d; asm("fma.rn.f32x2 %0, %1, %2, %3;" : "=l"(d) : "l"(a), "l"(b), "l"(c)); return d;
}
__device__ __forceinline__ ull mul2(ull a, ull b) {
    ull d; asm("mul.rn.f32x2 %0, %1, %2;" : "=l"(d) : "l"(a), "l"(b)); return d;
}

__device__ __forceinline__ float gelu_eps(float x) {
    // exact (erf-based) GELU, matching jax.nn.gelu(approximate=False), plus EPS
    return 0.5f * x * (1.0f + erff(x * 0.70710678118654752f)) + EPSF;
}

// =====================================================================
// Kernel 1: per (bh, split): kp = gelu(K @ P^T)+eps;
//           ctx_partial += kp^T @ V;  ksum_partial += colsum(kp)
// =====================================================================
__global__ __launch_bounds__(256) void perf_ctx_kernel(
    const float* __restrict__ Kg_, const float* __restrict__ Vg_,
    const float* __restrict__ Pg)
{
    extern __shared__ float sm[];
    float* Pt  = sm;                   // [DD][MM]  P transposed: Pt[d][m]
    float* Ks  = Pt + DD * MM;         // [TN][DD]
    float* Vs  = Ks + TN * DD;         // [TN][DD]
    float* KPs = Vs + TN * DD;         // [TN][MM]

    const int tid = threadIdx.x;
    const int bh = blockIdx.y, sp = blockIdx.x;
    const float* Kg = Kg_ + ((size_t)bh * NN + (size_t)sp * NCHUNK) * DD;
    const float* Vg = Vg_ + ((size_t)bh * NN + (size_t)sp * NCHUNK) * DD;

    // Build Pt (transposed projection) once
    for (int i = tid; i < MM * DD; i += 256) {
        int m = i >> 6, d = i & 63;
        Pt[d * MM + m] = Pg[i];
    }

    // GEMM1 mapping: whole warp shares one n-group (broadcast K loads)
    const int mg1 = tid & 31, ng1 = tid >> 5;
    const int m0a = mg1 * 8, n0a = ng1 * 4;
    // GEMM2 mapping: 8x8 ctx tile per thread (packed along d)
    const int dg2 = tid & 7, mg2 = tid >> 3;
    const int d0b = dg2 * 8, m0b = mg2 * 8;

    ull ctx2[8][4];
    float ksum_l[8];
    #pragma unroll
    for (int i = 0; i < 8; i++) {
        ksum_l[i] = 0.0f;
        #pragma unroll
        for (int j = 0; j < 4; j++) ctx2[i][j] = 0ull;  // two packed +0.0f
    }

    for (int nt = 0; nt < NCHUNK / TN; nt++) {
        const float4* Kg4 = reinterpret_cast<const float4*>(Kg + (size_t)nt * TN * DD);
        const float4* Vg4 = reinterpret_cast<const float4*>(Vg + (size_t)nt * TN * DD);
        for (int i = tid; i < TN * DD / 4; i += 256) {
            reinterpret_cast<float4*>(Ks)[i] = Kg4[i];
            reinterpret_cast<float4*>(Vs)[i] = Vg4[i];
        }
        __syncthreads();

        // ---- GEMM1: kp[TN][MM] = K[TN][DD] @ Pt ----
        ull a2[4][4];
        #pragma unroll
        for (int i = 0; i < 4; i++)
            #pragma unroll
            for (int j = 0; j < 4; j++) a2[i][j] = 0ull;

        #pragma unroll 8
        for (int d = 0; d < DD; d++) {
            ull kb[4];
            #pragma unroll
            for (int i = 0; i < 4; i++) {
                float kv = Ks[(n0a + i) * DD + d];   // warp-broadcast
                kb[i] = pack2(kv, kv);
            }
            ull p2[4];
            #pragma unroll
            for (int j = 0; j < 4; j++)
                p2[j] = *reinterpret_cast<const ull*>(&Pt[d * MM + m0a + 2 * j]);
            #pragma unroll
            for (int i = 0; i < 4; i++)
                #pragma unroll
                for (int j = 0; j < 4; j++)
                    a2[i][j] = fma2(kb[i], p2[j], a2[i][j]);
        }
        // gelu + eps, store kp tile
        #pragma unroll
        for (int i = 0; i < 4; i++) {
            #pragma unroll
            for (int j = 0; j < 4; j++) {
                float x0, x1; unpack2(a2[i][j], x0, x1);
                *reinterpret_cast<ull*>(&KPs[(n0a + i) * MM + m0a + 2 * j]) =
                    pack2(gelu_eps(x0), gelu_eps(x1));
            }
        }
        __syncthreads();

        // ---- GEMM2: ctx += kp^T @ V ; ksum += colsum(kp) ----
        #pragma unroll 2
        for (int n = 0; n < TN; n++) {
            float kpv[8];
            #pragma unroll
            for (int j = 0; j < 4; j++) {
                ull t = *reinterpret_cast<const ull*>(&KPs[n * MM + m0b + 2 * j]);
                unpack2(t, kpv[2 * j], kpv[2 * j + 1]);
            }
            ull v2[4];
            #pragma unroll
            for (int j = 0; j < 4; j++)
                v2[j] = *reinterpret_cast<const ull*>(&Vs[n * DD + d0b + 2 * j]);
            if (dg2 == 0) {
                #pragma unroll
                for (int mi = 0; mi < 8; mi++) ksum_l[mi] += kpv[mi];
            }
            #pragma unroll
            for (int mi = 0; mi < 8; mi++) {
                ull kb = pack2(kpv[mi], kpv[mi]);
                #pragma unroll
                for (int j = 0; j < 4; j++)
                    ctx2[mi][j] = fma2(kb, v2[j], ctx2[mi][j]);
            }
        }
        __syncthreads();
    }

    // write partials
    float* op = g_ctxp + ((size_t)(bh * NSPLIT) + sp) * MM * DD;
    #pragma unroll
    for (int mi = 0; mi < 8; mi++)
        #pragma unroll
        for (int j = 0; j < 4; j++)
            *reinterpret_cast<ull*>(&op[(m0b + mi) * DD + d0b + 2 * j]) = ctx2[mi][j];
    if (dg2 == 0) {
        float* kp_ = g_ksump + ((size_t)bh * NSPLIT + sp) * MM;
        #pragma unroll
        for (int mi = 0; mi < 8; mi++) kp_[m0b + mi] = ksum_l[mi];
    }
}

// =====================================================================
// Kernel R: deterministic reduction of split partials
// =====================================================================
__global__ __launch_bounds__(256) void perf_reduce_kernel()
{
    const int bh = blockIdx.x, tid = threadIdx.x;
    const float* src = g_ctxp + (size_t)bh * NSPLIT * MM * DD;
    float* dst = g_ctx + (size_t)bh * MM * DD;
    for (int i = tid; i < MM * DD; i += 256) {
        float s = 0.0f;
        #pragma unroll
        for (int sp = 0; sp < NSPLIT; sp++) s += src[(size_t)sp * MM * DD + i];
        dst[i] = s;
    }
    const float* srck = g_ksump + (size_t)bh * NSPLIT * MM;
    float* dstk = g_ksum + (size_t)bh * MM;
    for (int i = tid; i < MM; i += 256) {
        float s = 0.0f;
        #pragma unroll
        for (int sp = 0; sp < NSPLIT; sp++) s += srck[sp * MM + i];
        dstk[i] = s;
    }
}

// =====================================================================
// Kernel 2: qp = gelu(Q @ P^T)+eps; denom = qp.ksum; out = (qp @ ctx) / denom
// =====================================================================
#define QS_STRIDE 70   // padded row (conflict-free broadcast, 8B aligned)

__global__ __launch_bounds__(256) void perf_out_kernel(
    const float* __restrict__ Qg_, const float* __restrict__ Pg,
    float* __restrict__ Og_)
{
    extern __shared__ float sm[];
    float* Qs     = sm;                           // [TNQ][QS_STRIDE]
    float* QPs    = Qs + TNQ * QS_STRIDE;         // [TNQ][QS_STRIDE] (64 cols used)
    float* Ptc    = QPs + TNQ * QS_STRIDE;        // [DD][64]  chunk of P, transposed
    float* Cs     = Ptc + DD * 64;                // [64][DD]  chunk of ctx
    float* ksum_s = Cs + 64 * DD;                 // [64]
    float* denomS = ksum_s + 64;                  // [TNQ]

    const int tid = threadIdx.x;
    const int bh = blockIdx.y, qt = blockIdx.x;
    const float* Qg = Qg_ + ((size_t)bh * NN + (size_t)qt * TNQ) * DD;
    float* Og = Og_ + ((size_t)bh * NN + (size_t)qt * TNQ) * DD;
    const float* Cg  = g_ctx + (size_t)bh * MM * DD;
    const float* KSg = g_ksum + (size_t)bh * MM;

    for (int i = tid; i < TNQ * DD; i += 256) {
        int n = i >> 6, d = i & 63;
        Qs[n * QS_STRIDE + d] = Qg[i];
    }

    const int ng = tid >> 3, xg = tid & 7;
    const int n0 = ng * 4, x0 = xg * 8;   // x0: m-offset in GEMM1, d-offset in GEMM2

    ull outa[4][4];
    float dena[4] = {0.f, 0.f, 0.f, 0.f};
    #pragma unroll
    for (int i = 0; i < 4; i++)
        #pragma unroll
        for (int j = 0; j < 4; j++) outa[i][j] = 0ull;

    for (int mc = 0; mc < MM / 64; mc++) {
        for (int i = tid; i < 64 * DD; i += 256) {
            int m = i >> 6, d = i & 63;
            Ptc[d * 64 + m] = Pg[(mc * 64 + m) * DD + d];
            Cs[i] = Cg[(size_t)mc * 64 * DD + i];
        }
        if (tid < 64) ksum_s[tid] = KSg[mc * 64 + tid];
        __syncthreads();

        // ---- GEMM1: qp[TNQ][64] = Q @ Ptc ----
        ull b2[4][4];
        #pragma unroll
        for (int i = 0; i < 4; i++)
            #pragma unroll
            for (int j = 0; j < 4; j++) b2[i][j] = 0ull;

        #pragma unroll 8
        for (int d = 0; d < DD; d++) {
            ull qb[4];
            #pragma unroll
            for (int i = 0; i < 4; i++) {
                float qv = Qs[(n0 + i) * QS_STRIDE + d];
                qb[i] = pack2(qv, qv);
            }
            ull p2[4];
            #pragma unroll
            for (int j = 0; j < 4; j++)
                p2[j] = *reinterpret_cast<const ull*>(&Ptc[d * 64 + x0 + 2 * j]);
            #pragma unroll
            for (int i = 0; i < 4; i++)
                #pragma unroll
                for (int j = 0; j < 4; j++)
                    b2[i][j] = fma2(qb[i], p2[j], b2[i][j]);
        }
        #pragma unroll
        for (int i = 0; i < 4; i++) {
            #pragma unroll
            for (int j = 0; j < 4; j++) {
                float x0v, x1v; unpack2(b2[i][j], x0v, x1v);
                *reinterpret_cast<ull*>(&QPs[(n0 + i) * QS_STRIDE + x0 + 2 * j]) =
                    pack2(gelu_eps(x0v), gelu_eps(x1v));
            }
        }
        __syncthreads();

        // ---- GEMM2: out += qp @ ctx_chunk ; denom += qp . ksum_chunk ----
        #pragma unroll 2
        for (int mp = 0; mp < 64; mp++) {
            float qp[4];
            #pragma unroll
            for (int i = 0; i < 4; i++) qp[i] = QPs[(n0 + i) * QS_STRIDE + mp];
            ull c2[4];
            #pragma unroll
            for (int j = 0; j < 4; j++)
                c2[j] = *reinterpret_cast<const ull*>(&Cs[mp * 64 + x0 + 2 * j]);
            if (xg == 0) {
                float ks = ksum_s[mp];
                #pragma unroll
                for (int i = 0; i < 4; i++) dena[i] = fmaf(qp[i], ks, dena[i]);
            }
            #pragma unroll
            for (int i = 0; i < 4; i++) {
                ull qb = pack2(qp[i], qp[i]);
                #pragma unroll
                for (int j = 0; j < 4; j++)
                    outa[i][j] = fma2(qb, c2[j], outa[i][j]);
            }
        }
        __syncthreads();
    }

    if (xg == 0) {
        #pragma unroll
        for (int i = 0; i < 4; i++) denomS[n0 + i] = dena[i];
    }
    __syncthreads();

    #pragma unroll
    for (int i = 0; i < 4; i++) {
        float dinv = 1.0f / denomS[n0 + i];
        ull dv = pack2(dinv, dinv);
        #pragma unroll
        for (int j = 0; j < 4; j++)
            *reinterpret_cast<ull*>(&Og[(n0 + i) * DD + x0 + 2 * j]) = mul2(outa[i][j], dv);
    }
}

// =====================================================================
// launch
// =====================================================================
extern "C" void kernel_launch(void* const* d_in, const int* in_sizes, int n_in,
                              void* d_out, int out_size)
{
    const float* q    = (const float*)d_in[0];
    const float* k    = (const float*)d_in[1];
    const float* v    = (const float*)d_in[2];
    const float* proj = (const float*)d_in[3];
    float* out = (float*)d_out;

    const int SMEM1 = (DD * MM + 2 * TN * DD + TN * MM) * (int)sizeof(float);       // 112 KB
    const int SMEM2 = (2 * TNQ * QS_STRIDE + 2 * 64 * DD + 64 + TNQ) * (int)sizeof(float); // ~103 KB

    cudaFuncSetAttribute(perf_ctx_kernel, cudaFuncAttributeMaxDynamicSharedMemorySize, SMEM1);
    cudaFuncSetAttribute(perf_out_kernel, cudaFuncAttributeMaxDynamicSharedMemorySize, SMEM2);

    perf_ctx_kernel<<<dim3(NSPLIT, BH), 256, SMEM1>>>(k, v, proj);
    perf_reduce_kernel<<<BH, 256>>>();
    perf_out_kernel<<<dim3(NN / TNQ, BH), 256, SMEM2>>>(q, proj, out);
}